// round 4
// baseline (speedup 1.0000x reference)
#include <cuda_runtime.h>
#include <cstdint>

// Chamfer distance: B=8, N=M=4096, D=3 — bidirectional single-pass.
// Each pair (p,g) evaluated ONCE: d = x2(p) + w(g) - 2 p.g  feeds both
// row-min (pred->gt) and col-min (gt->pred).  fp32-FMA work halved vs
// per-direction recompute.
//
// Layout per block (b, pchunk):  256 threads x 16 resident gt points = full
// 4096-gt set in registers (packed f32x2 pairs).  256 preds stream through
// shared (broadcast).  Col-min thread-local; row-min via per-pred warp
// shuffle-min + deferred cross-warp combine.  Cross-block col combine via
// per-batch last-block election; final scalar via global election.

constexpr int B       = 8;
constexpr int NPTS    = 4096;
constexpr int THREADS = 256;
constexpr int GPT     = 16;                 // gt points per thread (8 pairs)
constexpr int PCHUNK  = 256;                // preds per block
constexpr int PSPLIT  = NPTS / PCHUNK;      // 16
constexpr int NBLOCKS = B * PSPLIT;         // 128

__device__ float        g_colpart[B * PSPLIT * NPTS]; // per-chunk col partials
__device__ float        g_rowsum[B * PSPLIT];         // per-block row sums
__device__ float        g_batch[B];
__device__ unsigned int g_cnt_batch[B];
__device__ unsigned int g_cnt_final;

__device__ __forceinline__ uint64_t pack2(float lo, float hi) {
    uint64_t r; asm("mov.b64 %0, {%1,%2};" : "=l"(r) : "f"(lo), "f"(hi)); return r;
}
__device__ __forceinline__ uint64_t fma2(uint64_t a, uint64_t b, uint64_t c) {
    uint64_t d; asm("fma.rn.f32x2 %0, %1, %2, %3;" : "=l"(d) : "l"(a), "l"(b), "l"(c)); return d;
}
__device__ __forceinline__ uint64_t add2(uint64_t a, uint64_t b) {
    uint64_t d; asm("add.rn.f32x2 %0, %1, %2;" : "=l"(d) : "l"(a), "l"(b)); return d;
}
__device__ __forceinline__ void unpack2(uint64_t v, float& lo, float& hi) {
    asm("mov.b64 {%0,%1}, %2;" : "=f"(lo), "=f"(hi) : "l"(v));
}

__global__ __launch_bounds__(THREADS) void chamfer_bidir(
    const float* __restrict__ pred, const float* __restrict__ gt,
    float* __restrict__ out)
{
    __shared__ ulonglong2 sp[PCHUNK][2];   // per pred: {mxx,myy},{mzz,x2x2} 8KB
    __shared__ float      srow[PCHUNK][8]; // per-pred warp-level row partials 8KB
    __shared__ float      sred[8];
    __shared__ int        s_elect, s_elect2;

    const int bx  = blockIdx.x;
    const int b   = bx >> 4;
    const int pc  = bx & 15;
    const int tid = threadIdx.x;
    const int wid = tid >> 5, lid = tid & 31;

    // ---- resident gt points: 8 packed pairs in registers ----
    uint64_t gx[8], gy[8], gz[8], gw[8];
    {
        const float2* g = reinterpret_cast<const float2*>(
            gt + (size_t)b * NPTS * 3 + (size_t)tid * GPT * 3);
        #pragma unroll
        for (int q = 0; q < 8; ++q) {
            const float2 a = g[3 * q + 0];   // x0, y0
            const float2 c = g[3 * q + 1];   // z0, x1
            const float2 e = g[3 * q + 2];   // y1, z1
            gx[q] = pack2(a.x, c.y);
            gy[q] = pack2(a.y, e.x);
            gz[q] = pack2(c.x, e.y);
            gw[q] = pack2(fmaf(a.x, a.x, fmaf(a.y, a.y, c.x * c.x)),
                          fmaf(c.y, c.y, fmaf(e.x, e.x, e.y * e.y)));
        }
    }

    // ---- stage pred chunk, pre-packed ----
    {
        const float* pp = pred + (size_t)b * NPTS * 3 + (size_t)pc * PCHUNK * 3;
        const float px = pp[3 * tid + 0];
        const float py = pp[3 * tid + 1];
        const float pz = pp[3 * tid + 2];
        const float x2 = fmaf(px, px, fmaf(py, py, pz * pz));
        sp[tid][0] = make_ulonglong2(pack2(-2.0f * px, -2.0f * px),
                                     pack2(-2.0f * py, -2.0f * py));
        sp[tid][1] = make_ulonglong2(pack2(-2.0f * pz, -2.0f * pz),
                                     pack2(x2, x2));
    }
    __syncthreads();

    float cmin[GPT];
    #pragma unroll
    for (int i = 0; i < GPT; ++i) cmin[i] = 3.4e38f;

    // ---- main loop: stream 256 preds (broadcast), software-pipelined ----
    ulonglong2 A  = sp[0][0];
    ulonglong2 Bv = sp[0][1];
    for (int p = 0; p < PCHUNK; ++p) {
        const int pn = (p + 1 < PCHUNK) ? p + 1 : p;
        const ulonglong2 A2  = sp[pn][0];
        const ulonglong2 B2  = sp[pn][1];

        float rA = 3.4e38f, rB = 3.4e38f;
        #pragma unroll
        for (int q = 0; q < 8; ++q) {
            uint64_t t = add2(gw[q], Bv.y);          // w + x2
            t = fma2(Bv.x, gz[q], t);
            t = fma2(A.y,  gy[q], t);
            t = fma2(A.x,  gx[q], t);
            float d0, d1;
            unpack2(t, d0, d1);
            cmin[2 * q + 0] = fminf(cmin[2 * q + 0], d0);
            cmin[2 * q + 1] = fminf(cmin[2 * q + 1], d1);
            if (q & 1) rB = fminf(rB, fminf(d0, d1));
            else       rA = fminf(rA, fminf(d0, d1));
        }
        float rmin = fminf(rA, rB);
        #pragma unroll
        for (int off = 16; off; off >>= 1)
            rmin = fminf(rmin, __shfl_xor_sync(0xffffffffu, rmin, off));
        if (lid == 0) srow[p][wid] = rmin;           // exclusive slot, no sync

        A = A2; Bv = B2;
    }
    __syncthreads();

    // ---- finish row mins: thread tid owns pred tid (complete over all gts) ----
    float blockRowSum;
    {
        const float4 r0 = *reinterpret_cast<const float4*>(&srow[tid][0]);
        const float4 r1 = *reinterpret_cast<const float4*>(&srow[tid][4]);
        float rm = fminf(fminf(fminf(r0.x, r0.y), fminf(r0.z, r0.w)),
                         fminf(fminf(r1.x, r1.y), fminf(r1.z, r1.w)));
        float v = fmaxf(rm, 0.0f);
        #pragma unroll
        for (int off = 16; off; off >>= 1)
            v += __shfl_down_sync(0xffffffffu, v, off);
        __syncthreads();                    // srow reads done before sred reuse? (sred separate) — keep ordering
        if (lid == 0) sred[wid] = v;
        __syncthreads();
        float t = (lid < 8) ? sred[lid] : 0.0f;
        #pragma unroll
        for (int off = 4; off; off >>= 1)
            t += __shfl_down_sync(0xffffffffu, t, off);
        blockRowSum = t;                    // valid in warp 0 lane 0
    }
    if (tid == 0) g_rowsum[bx] = blockRowSum;

    // ---- write col partials (unclamped mins over this block's 256 preds) ----
    {
        float* cp = g_colpart + ((size_t)bx * NPTS) + (size_t)tid * GPT;
        #pragma unroll
        for (int i = 0; i < GPT; i += 4)
            *reinterpret_cast<float4*>(cp + i) =
                make_float4(cmin[i], cmin[i + 1], cmin[i + 2], cmin[i + 3]);
    }

    // ---- per-batch election: last of 16 blocks combines the batch ----
    __threadfence();
    if (tid == 0)
        s_elect = (atomicAdd(&g_cnt_batch[b], 1u) == (unsigned)(PSPLIT - 1));
    __syncthreads();
    if (!s_elect) return;
    __threadfence();

    {
        const float* cpb = g_colpart + (size_t)b * PSPLIT * NPTS;
        float csum = 0.0f;
        #pragma unroll 4
        for (int i = tid; i < NPTS; i += THREADS) {
            float m = 3.4e38f;
            #pragma unroll
            for (int k = 0; k < PSPLIT; ++k)
                m = fminf(m, __ldcg(cpb + (size_t)k * NPTS + i));
            csum += fmaxf(m, 0.0f);
        }
        if (tid < PSPLIT) csum += __ldcg(&g_rowsum[b * PSPLIT + tid]);

        #pragma unroll
        for (int off = 16; off; off >>= 1)
            csum += __shfl_down_sync(0xffffffffu, csum, off);
        if (lid == 0) sred[wid] = csum;
        __syncthreads();
        if (wid == 0) {
            float t = (lid < 8) ? sred[lid] : 0.0f;
            #pragma unroll
            for (int off = 4; off; off >>= 1)
                t += __shfl_down_sync(0xffffffffu, t, off);
            if (lid == 0) g_batch[b] = t;
        }
    }

    // ---- global election: last batch-leader writes the scalar ----
    __threadfence();
    if (tid == 0)
        s_elect2 = (atomicAdd(&g_cnt_final, 1u) == (unsigned)(B - 1));
    __syncthreads();
    if (!s_elect2) return;
    __threadfence();

    if (tid == 0) {
        float s = 0.0f;
        #pragma unroll
        for (int i = 0; i < B; ++i) s += __ldcg(&g_batch[i]);
        out[0] = s * (1.0f / (float)(B * NPTS));
        // reset counters for next graph replay
        g_cnt_final = 0;
        #pragma unroll
        for (int i = 0; i < B; ++i) g_cnt_batch[i] = 0;
    }
}

extern "C" void kernel_launch(void* const* d_in, const int* in_sizes, int n_in,
                              void* d_out, int out_size)
{
    const float* pred = (const float*)d_in[0];
    const float* gt   = (const float*)d_in[1];
    float* out        = (float*)d_out;

    chamfer_bidir<<<NBLOCKS, THREADS>>>(pred, gt, out);
}

// round 5
// speedup vs baseline: 1.0538x; 1.0538x over previous
#include <cuda_runtime.h>
#include <cstdint>

// Chamfer distance: B=8, N=M=4096, D=3 — bidirectional single-pass, round 5.
// Each pair evaluated ONCE: d = x2(p) + w(g) - 2 p.g feeds row-min and col-min.
// Block (b, pc, gs): 128 threads x 8 resident gts (1024 gts) vs 256 streamed
// preds.  Col-min thread-local; row-min via register-batched butterfly
// transpose-reduce (1 shuffle/pred amortized).  Partials combined by per-batch
// elected block, then global elected block.

constexpr int B       = 8;
constexpr int NPTS    = 4096;
constexpr int THREADS = 128;
constexpr int GPT     = 8;                       // resident gts per thread
constexpr int GTSB    = THREADS * GPT;           // 1024 gts per block
constexpr int GS      = NPTS / GTSB;             // 4 gt splits
constexpr int PCHUNK  = 256;                     // preds streamed per block
constexpr int PC      = NPTS / PCHUNK;           // 16 pred chunks
constexpr int NBLOCKS = B * PC * GS;             // 512
constexpr int GRP     = 16;                      // preds per transpose group

__device__ float        g_colpart[B * PC * NPTS];  // [b][pc][gt] unclamped
__device__ float        g_rowpart[B * GS * NPTS];  // [b][gs][pred] unclamped
__device__ float        g_batch[B];
__device__ unsigned int g_cnt_batch[B];
__device__ unsigned int g_cnt_final;

__device__ __forceinline__ uint64_t pack2(float lo, float hi) {
    uint64_t r; asm("mov.b64 %0, {%1,%2};" : "=l"(r) : "f"(lo), "f"(hi)); return r;
}
__device__ __forceinline__ uint64_t fma2(uint64_t a, uint64_t b, uint64_t c) {
    uint64_t d; asm("fma.rn.f32x2 %0, %1, %2, %3;" : "=l"(d) : "l"(a), "l"(b), "l"(c)); return d;
}
__device__ __forceinline__ uint64_t add2(uint64_t a, uint64_t b) {
    uint64_t d; asm("add.rn.f32x2 %0, %1, %2;" : "=l"(d) : "l"(a), "l"(b)); return d;
}
__device__ __forceinline__ void unpack2(uint64_t v, float& lo, float& hi) {
    asm("mov.b64 {%0,%1}, %2;" : "=f"(lo), "=f"(hi) : "l"(v));
}

__global__ __launch_bounds__(THREADS, 4) void chamfer_bidir(
    const float* __restrict__ pred, const float* __restrict__ gt,
    float* __restrict__ out)
{
    __shared__ ulonglong2 sp[PCHUNK][2];      // {mxx,myy},{mzz,x2x2}  8KB
    __shared__ float      srow[PCHUNK][4];    // per-pred per-warp row mins 4KB
    __shared__ float      sred[4];
    __shared__ int        s_e1, s_e2;

    const int bx  = blockIdx.x;
    const int gs  = bx & (GS - 1);
    const int pc  = (bx >> 2) & (PC - 1);
    const int b   = bx >> 6;
    const int tid = threadIdx.x;
    const int wid = tid >> 5, lid = tid & 31;

    // ---- stage 256 preds (2 per thread), pre-packed ----
    {
        const float2* pp = reinterpret_cast<const float2*>(
            pred + (size_t)b * NPTS * 3 + (size_t)pc * PCHUNK * 3);
        const float2 u0 = pp[3 * tid + 0];   // x0 y0
        const float2 u1 = pp[3 * tid + 1];   // z0 x1
        const float2 u2 = pp[3 * tid + 2];   // y1 z1
        const float x2a = fmaf(u0.x, u0.x, fmaf(u0.y, u0.y, u1.x * u1.x));
        const float x2b = fmaf(u1.y, u1.y, fmaf(u2.x, u2.x, u2.y * u2.y));
        sp[2 * tid + 0][0] = make_ulonglong2(pack2(-2.f * u0.x, -2.f * u0.x),
                                             pack2(-2.f * u0.y, -2.f * u0.y));
        sp[2 * tid + 0][1] = make_ulonglong2(pack2(-2.f * u1.x, -2.f * u1.x),
                                             pack2(x2a, x2a));
        sp[2 * tid + 1][0] = make_ulonglong2(pack2(-2.f * u1.y, -2.f * u1.y),
                                             pack2(-2.f * u2.x, -2.f * u2.x));
        sp[2 * tid + 1][1] = make_ulonglong2(pack2(-2.f * u2.y, -2.f * u2.y),
                                             pack2(x2b, x2b));
    }

    // ---- resident gt points: 4 packed pairs ----
    uint64_t gx[4], gy[4], gz[4], gw[4];
    {
        const float2* g = reinterpret_cast<const float2*>(
            gt + (size_t)b * NPTS * 3 + (size_t)(gs * GTSB + tid * GPT) * 3);
        #pragma unroll
        for (int q = 0; q < 4; ++q) {
            const float2 a = g[3 * q + 0];
            const float2 c = g[3 * q + 1];
            const float2 e = g[3 * q + 2];
            gx[q] = pack2(a.x, c.y);
            gy[q] = pack2(a.y, e.x);
            gz[q] = pack2(c.x, e.y);
            gw[q] = pack2(fmaf(a.x, a.x, fmaf(a.y, a.y, c.x * c.x)),
                          fmaf(c.y, c.y, fmaf(e.x, e.x, e.y * e.y)));
        }
    }
    __syncthreads();

    float cmin[GPT];
    #pragma unroll
    for (int i = 0; i < GPT; ++i) cmin[i] = 3.4e38f;

    // ---- main loop: 16 groups x 16 preds ----
    for (int grp = 0; grp < PCHUNK / GRP; ++grp) {
        float a[GRP];
        #pragma unroll
        for (int i = 0; i < GRP; ++i) {
            const int p = grp * GRP + i;
            const ulonglong2 A  = sp[p][0];
            const ulonglong2 Bv = sp[p][1];
            float rm0 = 3.4e38f, rm1 = 3.4e38f;
            #pragma unroll
            for (int q = 0; q < 4; ++q) {
                uint64_t t = add2(gw[q], Bv.y);       // w + x2
                t = fma2(Bv.x, gz[q], t);
                t = fma2(A.y,  gy[q], t);
                t = fma2(A.x,  gx[q], t);
                float d0, d1;
                unpack2(t, d0, d1);
                cmin[2 * q + 0] = fminf(cmin[2 * q + 0], d0);
                cmin[2 * q + 1] = fminf(cmin[2 * q + 1], d1);
                if (q & 1) rm1 = fminf(rm1, fminf(d0, d1));
                else       rm0 = fminf(rm0, fminf(d0, d1));
            }
            a[i] = fminf(rm0, rm1);
        }
        // Butterfly transpose-reduce: lane lid ends with warp-min for pred
        // grp*16 + (lid & 15).
        #pragma unroll
        for (int k = 1; k <= 8; k <<= 1) {
            const bool up = (lid & k) != 0;
            #pragma unroll
            for (int m = 0; m < GRP / (2 * k); ++m) {
                const float send = up ? a[2 * m] : a[2 * m + 1];
                const float t    = __shfl_xor_sync(0xffffffffu, send, k);
                a[m] = fminf(up ? a[2 * m + 1] : a[2 * m], t);
            }
        }
        a[0] = fminf(a[0], __shfl_xor_sync(0xffffffffu, a[0], 16));
        if (lid < GRP) srow[grp * GRP + lid][wid] = a[0];
    }
    __syncthreads();

    // ---- cross-warp row combine -> global row partials ----
    #pragma unroll
    for (int p = tid; p < PCHUNK; p += THREADS) {
        const float4 v = *reinterpret_cast<const float4*>(srow[p]);
        g_rowpart[(size_t)(b * GS + gs) * NPTS + pc * PCHUNK + p] =
            fminf(fminf(v.x, v.y), fminf(v.z, v.w));
    }

    // ---- col partials -> global ----
    {
        float* cp = g_colpart + (size_t)(b * PC + pc) * NPTS + gs * GTSB + tid * GPT;
        reinterpret_cast<float4*>(cp)[0] = make_float4(cmin[0], cmin[1], cmin[2], cmin[3]);
        reinterpret_cast<float4*>(cp)[1] = make_float4(cmin[4], cmin[5], cmin[6], cmin[7]);
    }

    // ---- per-batch election (last of 64 blocks) ----
    __threadfence();
    if (tid == 0)
        s_e1 = (atomicAdd(&g_cnt_batch[b], 1u) == (unsigned)(PC * GS - 1));
    __syncthreads();
    if (!s_e1) return;
    __threadfence();

    {
        float sum = 0.0f;
        const float4* cpb = reinterpret_cast<const float4*>(g_colpart + (size_t)b * PC * NPTS);
        for (int g4 = tid; g4 < NPTS / 4; g4 += THREADS) {
            float4 m = __ldcg(&cpb[g4]);
            #pragma unroll
            for (int k = 1; k < PC; ++k) {
                const float4 v = __ldcg(&cpb[(size_t)k * (NPTS / 4) + g4]);
                m.x = fminf(m.x, v.x); m.y = fminf(m.y, v.y);
                m.z = fminf(m.z, v.z); m.w = fminf(m.w, v.w);
            }
            sum += fmaxf(m.x, 0.f) + fmaxf(m.y, 0.f) + fmaxf(m.z, 0.f) + fmaxf(m.w, 0.f);
        }
        const float4* rpb = reinterpret_cast<const float4*>(g_rowpart + (size_t)b * GS * NPTS);
        for (int p4 = tid; p4 < NPTS / 4; p4 += THREADS) {
            float4 m = __ldcg(&rpb[p4]);
            #pragma unroll
            for (int k = 1; k < GS; ++k) {
                const float4 v = __ldcg(&rpb[(size_t)k * (NPTS / 4) + p4]);
                m.x = fminf(m.x, v.x); m.y = fminf(m.y, v.y);
                m.z = fminf(m.z, v.z); m.w = fminf(m.w, v.w);
            }
            sum += fmaxf(m.x, 0.f) + fmaxf(m.y, 0.f) + fmaxf(m.z, 0.f) + fmaxf(m.w, 0.f);
        }
        #pragma unroll
        for (int off = 16; off; off >>= 1)
            sum += __shfl_down_sync(0xffffffffu, sum, off);
        if (lid == 0) sred[wid] = sum;
        __syncthreads();
        if (tid == 0)
            g_batch[b] = (sred[0] + sred[1]) + (sred[2] + sred[3]);
    }
    __syncthreads();

    // ---- global election (last of 8 batch leaders) ----
    __threadfence();
    if (tid == 0)
        s_e2 = (atomicAdd(&g_cnt_final, 1u) == (unsigned)(B - 1));
    __syncthreads();
    if (!s_e2) return;

    if (tid == 0) {
        __threadfence();
        float s = 0.0f;
        #pragma unroll
        for (int i = 0; i < B; ++i) s += __ldcg(&g_batch[i]);
        out[0] = s * (1.0f / (float)(B * NPTS));
        g_cnt_final = 0;
        #pragma unroll
        for (int i = 0; i < B; ++i) g_cnt_batch[i] = 0;
    }
}

extern "C" void kernel_launch(void* const* d_in, const int* in_sizes, int n_in,
                              void* d_out, int out_size)
{
    const float* pred = (const float*)d_in[0];
    const float* gt   = (const float*)d_in[1];
    float* out        = (float*)d_out;

    chamfer_bidir<<<NBLOCKS, THREADS>>>(pred, gt, out);
}

// round 6
// speedup vs baseline: 1.0845x; 1.0292x over previous
#include <cuda_runtime.h>
#include <cstdint>

// Chamfer distance: B=8, N=M=4096, D=3 — bidirectional single-pass, round 6.
// Each pair evaluated ONCE: e = x2(p) + w(g) - 2 p.g; row-min over g gives
// dist1(p), col-min over p gives dist2(g).
// R6 = R5 with the forced 128-reg cap removed (spill fix) + tree row-min.

constexpr int B       = 8;
constexpr int NPTS    = 4096;
constexpr int THREADS = 128;
constexpr int GPT     = 8;                       // resident gts per thread
constexpr int GTSB    = THREADS * GPT;           // 1024 gts per block
constexpr int GS      = NPTS / GTSB;             // 4 gt splits
constexpr int PCHUNK  = 256;                     // preds streamed per block
constexpr int PC      = NPTS / PCHUNK;           // 16 pred chunks
constexpr int NBLOCKS = B * PC * GS;             // 512
constexpr int GRP     = 16;                      // preds per transpose group

__device__ float        g_colpart[B * PC * NPTS];  // [b][pc][gt] unclamped
__device__ float        g_rowpart[B * GS * NPTS];  // [b][gs][pred] unclamped
__device__ float        g_batch[B];
__device__ unsigned int g_cnt_batch[B];
__device__ unsigned int g_cnt_final;

__device__ __forceinline__ uint64_t pack2(float lo, float hi) {
    uint64_t r; asm("mov.b64 %0, {%1,%2};" : "=l"(r) : "f"(lo), "f"(hi)); return r;
}
__device__ __forceinline__ uint64_t fma2(uint64_t a, uint64_t b, uint64_t c) {
    uint64_t d; asm("fma.rn.f32x2 %0, %1, %2, %3;" : "=l"(d) : "l"(a), "l"(b), "l"(c)); return d;
}
__device__ __forceinline__ uint64_t add2(uint64_t a, uint64_t b) {
    uint64_t d; asm("add.rn.f32x2 %0, %1, %2;" : "=l"(d) : "l"(a), "l"(b)); return d;
}
__device__ __forceinline__ void unpack2(uint64_t v, float& lo, float& hi) {
    asm("mov.b64 {%0,%1}, %2;" : "=f"(lo), "=f"(hi) : "l"(v));
}

__global__ __launch_bounds__(THREADS) void chamfer_bidir(
    const float* __restrict__ pred, const float* __restrict__ gt,
    float* __restrict__ out)
{
    __shared__ ulonglong2 sp[PCHUNK][2];      // {mxx,myy},{mzz,x2x2}  8KB
    __shared__ float      srow[PCHUNK][4];    // per-pred per-warp row mins 4KB
    __shared__ float      sred[4];
    __shared__ int        s_e1, s_e2;

    const int bx  = blockIdx.x;
    const int gs  = bx & (GS - 1);
    const int pc  = (bx >> 2) & (PC - 1);
    const int b   = bx >> 6;
    const int tid = threadIdx.x;
    const int wid = tid >> 5, lid = tid & 31;

    // ---- stage 256 preds (2 per thread), pre-packed ----
    {
        const float2* pp = reinterpret_cast<const float2*>(
            pred + (size_t)b * NPTS * 3 + (size_t)pc * PCHUNK * 3);
        const float2 u0 = pp[3 * tid + 0];   // x0 y0
        const float2 u1 = pp[3 * tid + 1];   // z0 x1
        const float2 u2 = pp[3 * tid + 2];   // y1 z1
        const float x2a = fmaf(u0.x, u0.x, fmaf(u0.y, u0.y, u1.x * u1.x));
        const float x2b = fmaf(u1.y, u1.y, fmaf(u2.x, u2.x, u2.y * u2.y));
        sp[2 * tid + 0][0] = make_ulonglong2(pack2(-2.f * u0.x, -2.f * u0.x),
                                             pack2(-2.f * u0.y, -2.f * u0.y));
        sp[2 * tid + 0][1] = make_ulonglong2(pack2(-2.f * u1.x, -2.f * u1.x),
                                             pack2(x2a, x2a));
        sp[2 * tid + 1][0] = make_ulonglong2(pack2(-2.f * u1.y, -2.f * u1.y),
                                             pack2(-2.f * u2.x, -2.f * u2.x));
        sp[2 * tid + 1][1] = make_ulonglong2(pack2(-2.f * u2.y, -2.f * u2.y),
                                             pack2(x2b, x2b));
    }

    // ---- resident gt points: 4 packed pairs ----
    uint64_t gx[4], gy[4], gz[4], gw[4];
    {
        const float2* g = reinterpret_cast<const float2*>(
            gt + (size_t)b * NPTS * 3 + (size_t)(gs * GTSB + tid * GPT) * 3);
        #pragma unroll
        for (int q = 0; q < 4; ++q) {
            const float2 a = g[3 * q + 0];
            const float2 c = g[3 * q + 1];
            const float2 e = g[3 * q + 2];
            gx[q] = pack2(a.x, c.y);
            gy[q] = pack2(a.y, e.x);
            gz[q] = pack2(c.x, e.y);
            gw[q] = pack2(fmaf(a.x, a.x, fmaf(a.y, a.y, c.x * c.x)),
                          fmaf(c.y, c.y, fmaf(e.x, e.x, e.y * e.y)));
        }
    }
    __syncthreads();

    float cmin[GPT];
    #pragma unroll
    for (int i = 0; i < GPT; ++i) cmin[i] = 3.4e38f;

    // ---- main loop: 16 groups x 16 preds ----
    for (int grp = 0; grp < PCHUNK / GRP; ++grp) {
        float a[GRP];
        #pragma unroll
        for (int i = 0; i < GRP; ++i) {
            const int p = grp * GRP + i;
            const ulonglong2 A  = sp[p][0];
            const ulonglong2 Bv = sp[p][1];
            float m01[4];
            #pragma unroll
            for (int q = 0; q < 4; ++q) {
                uint64_t t = add2(gw[q], Bv.y);       // w + x2
                t = fma2(Bv.x, gz[q], t);
                t = fma2(A.y,  gy[q], t);
                t = fma2(A.x,  gx[q], t);
                float d0, d1;
                unpack2(t, d0, d1);
                cmin[2 * q + 0] = fminf(cmin[2 * q + 0], d0);
                cmin[2 * q + 1] = fminf(cmin[2 * q + 1], d1);
                m01[q] = fminf(d0, d1);
            }
            a[i] = fminf(fminf(m01[0], m01[1]), fminf(m01[2], m01[3]));
        }
        // Butterfly transpose-reduce: lane lid ends with warp-min for pred
        // grp*16 + (lid & 15).
        #pragma unroll
        for (int k = 1; k <= 8; k <<= 1) {
            const bool up = (lid & k) != 0;
            #pragma unroll
            for (int m = 0; m < GRP / (2 * k); ++m) {
                const float send = up ? a[2 * m] : a[2 * m + 1];
                const float t    = __shfl_xor_sync(0xffffffffu, send, k);
                a[m] = fminf(up ? a[2 * m + 1] : a[2 * m], t);
            }
        }
        a[0] = fminf(a[0], __shfl_xor_sync(0xffffffffu, a[0], 16));
        if (lid < GRP) srow[grp * GRP + lid][wid] = a[0];
    }
    __syncthreads();

    // ---- cross-warp row combine -> global row partials ----
    #pragma unroll
    for (int p = tid; p < PCHUNK; p += THREADS) {
        const float4 v = *reinterpret_cast<const float4*>(srow[p]);
        g_rowpart[(size_t)(b * GS + gs) * NPTS + pc * PCHUNK + p] =
            fminf(fminf(v.x, v.y), fminf(v.z, v.w));
    }

    // ---- col partials -> global ----
    {
        float* cp = g_colpart + (size_t)(b * PC + pc) * NPTS + gs * GTSB + tid * GPT;
        reinterpret_cast<float4*>(cp)[0] = make_float4(cmin[0], cmin[1], cmin[2], cmin[3]);
        reinterpret_cast<float4*>(cp)[1] = make_float4(cmin[4], cmin[5], cmin[6], cmin[7]);
    }

    // ---- per-batch election (last of 64 blocks) ----
    __threadfence();
    if (tid == 0)
        s_e1 = (atomicAdd(&g_cnt_batch[b], 1u) == (unsigned)(PC * GS - 1));
    __syncthreads();
    if (!s_e1) return;
    __threadfence();

    {
        float sum = 0.0f;
        const float4* cpb = reinterpret_cast<const float4*>(g_colpart + (size_t)b * PC * NPTS);
        for (int g4 = tid; g4 < NPTS / 4; g4 += THREADS) {
            float4 m = __ldcg(&cpb[g4]);
            #pragma unroll
            for (int k = 1; k < PC; ++k) {
                const float4 v = __ldcg(&cpb[(size_t)k * (NPTS / 4) + g4]);
                m.x = fminf(m.x, v.x); m.y = fminf(m.y, v.y);
                m.z = fminf(m.z, v.z); m.w = fminf(m.w, v.w);
            }
            sum += fmaxf(m.x, 0.f) + fmaxf(m.y, 0.f) + fmaxf(m.z, 0.f) + fmaxf(m.w, 0.f);
        }
        const float4* rpb = reinterpret_cast<const float4*>(g_rowpart + (size_t)b * GS * NPTS);
        for (int p4 = tid; p4 < NPTS / 4; p4 += THREADS) {
            float4 m = __ldcg(&rpb[p4]);
            #pragma unroll
            for (int k = 1; k < GS; ++k) {
                const float4 v = __ldcg(&rpb[(size_t)k * (NPTS / 4) + p4]);
                m.x = fminf(m.x, v.x); m.y = fminf(m.y, v.y);
                m.z = fminf(m.z, v.z); m.w = fminf(m.w, v.w);
            }
            sum += fmaxf(m.x, 0.f) + fmaxf(m.y, 0.f) + fmaxf(m.z, 0.f) + fmaxf(m.w, 0.f);
        }
        #pragma unroll
        for (int off = 16; off; off >>= 1)
            sum += __shfl_down_sync(0xffffffffu, sum, off);
        if (lid == 0) sred[wid] = sum;
        __syncthreads();
        if (tid == 0)
            g_batch[b] = (sred[0] + sred[1]) + (sred[2] + sred[3]);
    }
    __syncthreads();

    // ---- global election (last of 8 batch leaders) ----
    __threadfence();
    if (tid == 0)
        s_e2 = (atomicAdd(&g_cnt_final, 1u) == (unsigned)(B - 1));
    __syncthreads();
    if (!s_e2) return;

    if (tid == 0) {
        __threadfence();
        float s = 0.0f;
        #pragma unroll
        for (int i = 0; i < B; ++i) s += __ldcg(&g_batch[i]);
        out[0] = s * (1.0f / (float)(B * NPTS));
        g_cnt_final = 0;
        #pragma unroll
        for (int i = 0; i < B; ++i) g_cnt_batch[i] = 0;
    }
}

extern "C" void kernel_launch(void* const* d_in, const int* in_sizes, int n_in,
                              void* d_out, int out_size)
{
    const float* pred = (const float*)d_in[0];
    const float* gt   = (const float*)d_in[1];
    float* out        = (float*)d_out;

    chamfer_bidir<<<NBLOCKS, THREADS>>>(pred, gt, out);
}